// round 6
// baseline (speedup 1.0000x reference)
#include <cuda_runtime.h>
#include <cuda_bf16.h>

#define B_ 256
#define N_ 1024
#define NT 1024              // tiles of 128 pairs

#define PRED_OFF (B_*11*N_)                  // 2883584
#define NORM_OFF (PRED_OFF + B_*N_*11*2)     // 8650752

// smem byte offsets (dynamic, all swizzled chunk^(row&7) layouts)
//   X buffers: buf p at p*65536  (hi 32768 | lo 32768), rows of 256B
#define OW1H 131072          // W1T hi: 128 rows x 256B
#define OW1L 163840
#define OW2  196608          // 4 x 8192: cn_hi, cn_lo, bn_hi, bn_lo (rows of 128B)
#define OT   229376
#define OB1  229888
#define OB2  230400
#define OLW  230912
#define DSMEM_BYTES 231424

typedef unsigned long long u64;
typedef unsigned int u32;

// ---------------- persistent device scratch ----------------
__device__ __align__(16) __nv_bfloat16 g_eh[2][(size_t)B_ * N_ * 64];  // embeddings hi
__device__ __align__(16) __nv_bfloat16 g_el[2][(size_t)B_ * N_ * 64];  // embeddings lo
__device__ unsigned char g_v[2][B_ * N_];
__device__ __align__(16) __nv_bfloat16 g_W1hi[16384];   // W1T fused [j=128][k=128]
__device__ __align__(16) __nv_bfloat16 g_W1lo[16384];
__device__ __align__(16) __nv_bfloat16 g_W2i[4][4096];  // cn_hi, cn_lo, bn_hi, bn_lo [j=64][k=64]
__device__ float g_B1[128], g_B2[128], g_T[128];

// ---------------- helpers ----------------
__device__ __forceinline__ u32 smem_u32(const void* p) {
    u32 a; asm("{ .reg .u64 t; cvta.to.shared.u64 t, %1; cvt.u32.u64 %0, t; }" : "=r"(a) : "l"(p));
    return a;
}
__device__ __forceinline__ void ldsm4(u32 addr, u32& r0, u32& r1, u32& r2, u32& r3) {
    asm volatile("ldmatrix.sync.aligned.m8n8.x4.shared.b16 {%0,%1,%2,%3}, [%4];"
        : "=r"(r0), "=r"(r1), "=r"(r2), "=r"(r3) : "r"(addr));
}
__device__ __forceinline__ void mma16816(float* c, const u32* a, u32 b0, u32 b1) {
    asm volatile("mma.sync.aligned.m16n8k16.row.col.f32.bf16.bf16.f32 "
        "{%0,%1,%2,%3}, {%4,%5,%6,%7}, {%8,%9}, {%0,%1,%2,%3};"
        : "+f"(c[0]), "+f"(c[1]), "+f"(c[2]), "+f"(c[3])
        : "r"(a[0]), "r"(a[1]), "r"(a[2]), "r"(a[3]), "r"(b0), "r"(b1));
}
__device__ __forceinline__ void cpasync16(u32 dst, const void* src) {
    asm volatile("cp.async.cg.shared.global [%0], [%1], 16;" :: "r"(dst), "l"(src));
}
__device__ __forceinline__ void cpcommit() { asm volatile("cp.async.commit_group;" ::: "memory"); }
__device__ __forceinline__ void cpwait0()  { asm volatile("cp.async.wait_group 0;"  ::: "memory"); }

__device__ __forceinline__ u32 pkhi(float a, float b, u32& lopk) {
    __nv_bfloat16 ha = __float2bfloat16(a), hb = __float2bfloat16(b);
    __nv_bfloat16 la = __float2bfloat16(a - __bfloat162float(ha));
    __nv_bfloat16 lb = __float2bfloat16(b - __bfloat162float(hb));
    __nv_bfloat162 H = __halves2bfloat162(ha, hb), L = __halves2bfloat162(la, lb);
    lopk = *(u32*)&L;
    return *(u32*)&H;
}

// ---------------- weight preprocessing ----------------
__global__ void prep_kernel(const float* cnW1, const float* bnW1,
                            const float* cnW2, const float* bnW2,
                            const float* cnb1, const float* bnb1,
                            const float* cnb2, const float* bnb2,
                            const float* lab) {
    int t = threadIdx.x;
    for (int i = t; i < 128 * 128; i += 256) {
        int j = i >> 7, k = i & 127;        // transposed image [j][k]
        float a = (j < 64) ? cnW1[k * 64 + j] : bnW1[k * 64 + (j - 64)];
        __nv_bfloat16 h = __float2bfloat16(a);
        g_W1hi[i] = h;
        g_W1lo[i] = __float2bfloat16(a - __bfloat162float(h));
    }
    for (int i = t; i < 4096; i += 256) {
        int j = i >> 6, k = i & 63;
        float a = cnW2[k * 64 + j];
        __nv_bfloat16 h = __float2bfloat16(a);
        g_W2i[0][i] = h;
        g_W2i[1][i] = __float2bfloat16(a - __bfloat162float(h));
        float bnv = bnW2[k * 64 + j];
        __nv_bfloat16 hb = __float2bfloat16(bnv);
        g_W2i[2][i] = hb;
        g_W2i[3][i] = __float2bfloat16(bnv - __bfloat162float(hb));
    }
    if (t < 64) {
        g_B1[t] = cnb1[t]; g_B1[64 + t] = bnb1[t];
        g_B2[t] = cnb2[t]; g_B2[64 + t] = bnb2[t];
    }
    if (t < 128) {
        int v = t >> 6, j = t & 63;
        float s = 0.f;
        for (int m = 0; m < 64; m++) s += lab[v * 64 + m] * bnW1[(128 + m) * 64 + j];
        g_T[t] = s;
    }
}

// ---------------- stage 0: embedding (bf16 hi/lo) + fused head ----------------
__global__ void stage0_kernel(const int* __restrict__ x, const float* __restrict__ y,
                              const float* __restrict__ embW, const float* __restrict__ embb,
                              const float* __restrict__ llrW, const float* __restrict__ llrb,
                              float* __restrict__ out) {
    int f = blockIdx.x * blockDim.x + threadIdx.x;
    int pos = f >> 4;
    int c4 = (f & 15) << 2;
    float y0 = y[pos * 2 + 0], y1 = y[pos * 2 + 1];
    float4 w0 = *(const float4*)(embW + c4);
    float4 w1 = *(const float4*)(embW + 64 + c4);
    float4 bb = *(const float4*)(embb + c4);
    float4 e;
    e.x = fmaf(y0, w0.x, fmaf(y1, w1.x, bb.x));
    e.y = fmaf(y0, w0.y, fmaf(y1, w1.y, bb.y));
    e.z = fmaf(y0, w0.z, fmaf(y1, w1.z, bb.z));
    e.w = fmaf(y0, w0.w, fmaf(y1, w1.w, bb.w));
    {
        u32 lo0, lo1;
        u32 h0 = pkhi(e.x, e.y, lo0);
        u32 h1 = pkhi(e.z, e.w, lo1);
        size_t ad = (size_t)pos * 64 + c4;
        *(u32*)(&g_eh[0][ad])     = h0;
        *(u32*)(&g_eh[0][ad + 2]) = h1;
        *(u32*)(&g_el[0][ad])     = lo0;
        *(u32*)(&g_el[0][ad + 2]) = lo1;
    }

    float4 wa = *(const float4*)(llrW + c4 * 2);
    float4 wb = *(const float4*)(llrW + c4 * 2 + 4);
    float l0 = e.x * wa.x + e.y * wa.z + e.z * wb.x + e.w * wb.z;
    float l1 = e.x * wa.y + e.y * wa.w + e.z * wb.y + e.w * wb.w;
    float nr = e.x * e.x + e.y * e.y + e.z * e.z + e.w * e.w;
    #pragma unroll
    for (int o = 8; o >= 1; o >>= 1) {
        l0 += __shfl_xor_sync(0xffffffffu, l0, o);
        l1 += __shfl_xor_sync(0xffffffffu, l1, o);
        nr += __shfl_xor_sync(0xffffffffu, nr, o);
    }
    if ((f & 15) == 0) {
        int v = x[pos];
        g_v[0][pos] = (unsigned char)v;
        l0 += llrb[0]; l1 += llrb[1];
        float m = fmaxf(l0, l1);
        float x0 = expf(l0 - m), x1 = expf(l1 - m);
        float inv = 1.f / (x0 + x1);
        float p0 = x0 * inv, p1 = x1 * inv;
        float pt = v ? p1 : p0;
        float loss = -logf(fminf(fmaxf(pt, 1e-7f), 1.f));
        int b = pos >> 10, p = pos & 1023;
        out[(size_t)b * (11 * N_) + p] = loss;
        float2* pr = (float2*)(out + PRED_OFF + (((size_t)(b * N_ + p)) * 11) * 2);
        *pr = make_float2(p0, p1);
        out[NORM_OFF + (size_t)b * (11 * N_) + p] = sqrtf(nr);
    }
}

// ---------------- main butterfly-stage kernel (mma.sync + cp.async pipeline) ----------------
__global__ void __launch_bounds__(256, 1)
stage_kernel(int scope, int srcb, int s,
             const float* __restrict__ llrW, const float* __restrict__ llrb,
             float* __restrict__ out) {
    extern __shared__ char smp[];
    const u32 smb = smem_u32(smp);
    float* sT  = (float*)(smp + OT);
    float* sB1 = (float*)(smp + OB1);
    float* sB2 = (float*)(smp + OB2);
    float* sLW = (float*)(smp + OLW);

    const int tid = threadIdx.x;
    const int half = scope >> 1;
    const int dstb = srcb ^ 1;

    {   // stage weights into swizzled smem images
        #pragma unroll
        for (int it = 0; it < 8; it++) {
            int i = tid + it * 256;                  // 2048 chunks per buffer
            int row = i >> 4, ck = i & 15;
            u32 ad = row * 256 + (((ck ^ (row & 7)) & 15) << 4);
            *(uint4*)(smp + OW1H + ad) = ((const uint4*)g_W1hi)[i];
            *(uint4*)(smp + OW1L + ad) = ((const uint4*)g_W1lo)[i];
            int mt = i >> 9, rem = i & 511;
            int r2 = rem >> 3, c2 = rem & 7;
            u32 ad2 = mt * 8192 + r2 * 128 + ((c2 ^ (r2 & 7)) << 4);
            *(uint4*)(smp + OW2 + ad2) = ((const uint4*)g_W2i)[i];
        }
        if (tid < 128) { sT[tid] = g_T[tid]; sB1[tid] = g_B1[tid]; sB2[tid] = g_B2[tid]; sLW[tid] = llrW[tid]; }
    }
    __syncthreads();

    const int w = tid >> 5, l = tid & 31;
    const int wm = w & 3, wn = w >> 2;       // 4m x 2n warp grid
    const int m0 = wm * 32;
    const int n0 = wn * 64;
    const int side = wn;
    const float lb0 = llrb[0], lb1 = llrb[1];

    const int ra   = l & 15;                 // ldmatrix A row within 16
    const int cko  = l >> 4;                 // A chunk offset
    const int rb   = (l & 7) + ((l >> 1) & 8);  // ldmatrix B row within 16
    const int ckbo = (l >> 3) & 1;           // B chunk offset
    const int cb8  = n0 >> 3;

    const __nv_bfloat16* gsh = g_eh[srcb];
    const __nv_bfloat16* gsl = g_el[srcb];

    // prefetch helper (lambda-free, expanded inline below)
    #define PREFETCH(TILE, BUF) do {                                            \
        int pb_ = (TILE) >> 2;                                                  \
        int pj0_ = ((TILE) & 3) << 7;                                           \
        int pr_ = tid & 127;                                                    \
        int phl_ = tid >> 7;                                                    \
        const __nv_bfloat16* psrc_ = phl_ ? gsl : gsh;                          \
        u32 pdst_ = smb + (BUF) * 65536 + phl_ * 32768 + pr_ * 256;             \
        int pj_ = pj0_ + pr_;                                                   \
        int pso_ = ((pj_ & ~(half - 1)) << 1) | (pj_ & (half - 1));             \
        const char* pp0_ = (const char*)(psrc_ + ((size_t)pb_ * N_ + pso_) * 64);        \
        const char* pp1_ = (const char*)(psrc_ + ((size_t)pb_ * N_ + pso_ + half) * 64); \
        int psw_ = pr_ & 7;                                                     \
        _Pragma("unroll")                                                       \
        for (int ck_ = 0; ck_ < 8; ck_++) {                                     \
            cpasync16(pdst_ + ((ck_ ^ psw_) << 4), pp0_ + (ck_ << 4));          \
            cpasync16(pdst_ + (((ck_ + 8) ^ psw_) << 4), pp1_ + (ck_ << 4));    \
        }                                                                       \
    } while (0)

    int buf = 0;
    int tile0 = blockIdx.x;
    if (tile0 < NT) { PREFETCH(tile0, 0); }
    cpcommit();

    for (int tile = tile0; tile < NT; tile += 152) {
        int b  = tile >> 2;
        int j0 = (tile & 3) << 7;
        const unsigned char* vb = g_v[srcb] + b * N_;

        // ---- per-thread bits (issued early, consumed in epilogues) ----
        int vx[2][2], vee[2][2];
        #pragma unroll
        for (int mt = 0; mt < 2; mt++)
            #pragma unroll
            for (int hh = 0; hh < 2; hh++) {
                int r = m0 + mt * 16 + (l >> 2) + hh * 8;
                int j = j0 + r;
                int so = ((j & ~(half - 1)) << 1) | (j & (half - 1));
                int vo = vb[so], v2 = vb[so + half];
                vx[mt][hh] = (vo + v2) & 1;
                vee[mt][hh] = v2;
            }

        cpwait0();
        __syncthreads();                      // current X buffer visible to all

        int nxt = tile + 152;
        if (nxt < NT) { PREFETCH(nxt, buf ^ 1); }
        cpcommit();

        const u32 xb  = smb + buf * 65536;    // X hi
        const u32 xbl = xb + 32768;           // X lo

        // ---- GEMM1: C[128x128] = X @ W1T^T, 3-term bf16 split ----
        float acc[2][8][4];
        #pragma unroll
        for (int mt = 0; mt < 2; mt++)
            #pragma unroll
            for (int nt = 0; nt < 8; nt++)
                #pragma unroll
                for (int q = 0; q < 4; q++) acc[mt][nt][q] = 0.f;

        #pragma unroll
        for (int kc = 0; kc < 8; kc++) {
            u32 ah[2][4], al[2][4];
            #pragma unroll
            for (int mt = 0; mt < 2; mt++) {
                int row = m0 + mt * 16 + ra;
                u32 ad = row * 256 + ((((kc * 2 + cko) ^ (row & 7)) & 15) << 4);
                ldsm4(xb + ad,  ah[mt][0], ah[mt][1], ah[mt][2], ah[mt][3]);
                ldsm4(xbl + ad, al[mt][0], al[mt][1], al[mt][2], al[mt][3]);
            }
            #pragma unroll
            for (int np = 0; np < 4; np++) {
                int row = n0 + np * 16 + rb;
                u32 bd = row * 256 + ((((kc * 2 + ckbo) ^ (row & 7)) & 15) << 4);
                u32 bh[4], bl[4];
                ldsm4(smb + OW1H + bd, bh[0], bh[1], bh[2], bh[3]);
                ldsm4(smb + OW1L + bd, bl[0], bl[1], bl[2], bl[3]);
                #pragma unroll
                for (int mt = 0; mt < 2; mt++) {
                    #pragma unroll
                    for (int hh = 0; hh < 2; hh++) {
                        float* c = acc[mt][np * 2 + hh];
                        mma16816(c, ah[mt], bh[2 * hh], bh[2 * hh + 1]);
                        mma16816(c, ah[mt], bl[2 * hh], bl[2 * hh + 1]);
                        mma16816(c, al[mt], bh[2 * hh], bh[2 * hh + 1]);
                    }
                }
            }
        }
        __syncthreads();   // all reads of X done before H overwrites it

        // ---- epilogue1: h = relu(C + b1 + T[vx]) -> H bf16 hi/lo into same buffer ----
        #pragma unroll
        for (int mt = 0; mt < 2; mt++) {
            int rowa = m0 + mt * 16 + (l >> 2);
            int rowb = rowa + 8;
            int va = vx[mt][0], vbt = vx[mt][1];
            #pragma unroll
            for (int nt = 0; nt < 8; nt++) {
                float* c = acc[mt][nt];
                int col = n0 + nt * 8 + (l & 3) * 2;
                float b0 = sB1[col], b1v = sB1[col + 1];
                float v00 = c[0] + b0, v01 = c[1] + b1v;
                float v10 = c[2] + b0, v11 = c[3] + b1v;
                if (side) {
                    int tcol = col - 64;
                    v00 += sT[va * 64 + tcol];  v01 += sT[va * 64 + tcol + 1];
                    v10 += sT[vbt * 64 + tcol]; v11 += sT[vbt * 64 + tcol + 1];
                }
                v00 = fmaxf(v00, 0.f); v01 = fmaxf(v01, 0.f);
                v10 = fmaxf(v10, 0.f); v11 = fmaxf(v11, 0.f);
                u32 lo0, lo1;
                u32 hi0 = pkhi(v00, v01, lo0);
                u32 hi1 = pkhi(v10, v11, lo1);
                int ck = cb8 + nt;
                u32 ada = rowa * 256 + (((ck ^ (rowa & 7)) & 15) << 4) + (l & 3) * 4;
                u32 adb = rowb * 256 + (((ck ^ (rowb & 7)) & 15) << 4) + (l & 3) * 4;
                *(u32*)(smp + (xb - smb) + ada)  = hi0;
                *(u32*)(smp + (xbl - smb) + ada) = lo0;
                *(u32*)(smp + (xb - smb) + adb)  = hi1;
                *(u32*)(smp + (xbl - smb) + adb) = lo1;
            }
        }
        __syncthreads();

        // ---- GEMM2: per side [128x64] = H_side @ W2_side, 3-term split ----
        float acc2[2][8][4];
        #pragma unroll
        for (int mt = 0; mt < 2; mt++)
            #pragma unroll
            for (int nt = 0; nt < 8; nt++)
                #pragma unroll
                for (int q = 0; q < 4; q++) acc2[mt][nt][q] = 0.f;

        const u32 w2hi = smb + OW2 + side * 16384;
        const u32 w2lo = w2hi + 8192;
        #pragma unroll
        for (int kc = 0; kc < 4; kc++) {
            u32 ah[2][4], al[2][4];
            #pragma unroll
            for (int mt = 0; mt < 2; mt++) {
                int row = m0 + mt * 16 + ra;
                int ck = side * 8 + kc * 2 + cko;
                u32 ad = row * 256 + ((((ck) ^ (row & 7)) & 15) << 4);
                ldsm4(xb + ad,  ah[mt][0], ah[mt][1], ah[mt][2], ah[mt][3]);
                ldsm4(xbl + ad, al[mt][0], al[mt][1], al[mt][2], al[mt][3]);
            }
            #pragma unroll
            for (int np = 0; np < 4; np++) {
                int row = np * 16 + rb;
                int ck = kc * 2 + ckbo;
                u32 bd = row * 128 + (((ck ^ (row & 7)) & 7) << 4);
                u32 bh[4], bl[4];
                ldsm4(w2hi + bd, bh[0], bh[1], bh[2], bh[3]);
                ldsm4(w2lo + bd, bl[0], bl[1], bl[2], bl[3]);
                #pragma unroll
                for (int mt = 0; mt < 2; mt++) {
                    #pragma unroll
                    for (int hh = 0; hh < 2; hh++) {
                        float* c = acc2[mt][np * 2 + hh];
                        mma16816(c, ah[mt], bh[2 * hh], bh[2 * hh + 1]);
                        mma16816(c, ah[mt], bl[2 * hh], bl[2 * hh + 1]);
                        mma16816(c, al[mt], bh[2 * hh], bh[2 * hh + 1]);
                    }
                }
            }
        }

        // ---- epilogue2: bias + e' (bf16 hi/lo) + fused head ----
        {
            float L0[2][2], L1[2][2], NR[2][2];
            #pragma unroll
            for (int mt = 0; mt < 2; mt++)
                #pragma unroll
                for (int hh = 0; hh < 2; hh++) { L0[mt][hh] = 0.f; L1[mt][hh] = 0.f; NR[mt][hh] = 0.f; }

            #pragma unroll
            for (int mt = 0; mt < 2; mt++) {
                int rowa = m0 + mt * 16 + (l >> 2);
                int pa = ((j0 + rowa) << 1) | side;
                int pb = ((j0 + rowa + 8) << 1) | side;
                size_t eaad = ((size_t)b * N_ + pa) * 64;
                size_t ebad = ((size_t)b * N_ + pb) * 64;
                #pragma unroll
                for (int nt = 0; nt < 8; nt++) {
                    float* c = acc2[mt][nt];
                    int col = nt * 8 + (l & 3) * 2;
                    float b0 = sB2[side * 64 + col], b1v = sB2[side * 64 + col + 1];
                    float o00 = c[0] + b0, o01 = c[1] + b1v;
                    float o10 = c[2] + b0, o11 = c[3] + b1v;
                    u32 lo0, lo1;
                    u32 hi0 = pkhi(o00, o01, lo0);
                    u32 hi1 = pkhi(o10, o11, lo1);
                    *(u32*)(&g_eh[dstb][eaad + col]) = hi0;
                    *(u32*)(&g_el[dstb][eaad + col]) = lo0;
                    *(u32*)(&g_eh[dstb][ebad + col]) = hi1;
                    *(u32*)(&g_el[dstb][ebad + col]) = lo1;
                    float w0 = sLW[col * 2], w1 = sLW[col * 2 + 1];
                    float w2 = sLW[col * 2 + 2], w3 = sLW[col * 2 + 3];
                    L0[mt][0] += o00 * w0 + o01 * w2;
                    L1[mt][0] += o00 * w1 + o01 * w3;
                    NR[mt][0] += o00 * o00 + o01 * o01;
                    L0[mt][1] += o10 * w0 + o11 * w2;
                    L1[mt][1] += o10 * w1 + o11 * w3;
                    NR[mt][1] += o10 * o10 + o11 * o11;
                }
            }
            #pragma unroll
            for (int off = 2; off >= 1; off >>= 1) {
                #pragma unroll
                for (int mt = 0; mt < 2; mt++)
                    #pragma unroll
                    for (int hh = 0; hh < 2; hh++) {
                        L0[mt][hh] += __shfl_xor_sync(0xffffffffu, L0[mt][hh], off);
                        L1[mt][hh] += __shfl_xor_sync(0xffffffffu, L1[mt][hh], off);
                        NR[mt][hh] += __shfl_xor_sync(0xffffffffu, NR[mt][hh], off);
                    }
            }
            if ((l & 3) == 0) {
                #pragma unroll
                for (int mt = 0; mt < 2; mt++) {
                    #pragma unroll
                    for (int hh = 0; hh < 2; hh++) {
                        int r = m0 + mt * 16 + (l >> 2) + hh * 8;
                        int p = ((j0 + r) << 1) | side;
                        unsigned char vp = (unsigned char)(side ? vee[mt][hh] : vx[mt][hh]);
                        g_v[dstb][b * N_ + p] = vp;
                        float l0 = L0[mt][hh] + lb0, l1 = L1[mt][hh] + lb1;
                        float mm = fmaxf(l0, l1);
                        float x0 = expf(l0 - mm), x1 = expf(l1 - mm);
                        float inv = 1.f / (x0 + x1);
                        float p0 = x0 * inv, p1 = x1 * inv;
                        float pt = vp ? p1 : p0;
                        float loss = -logf(fminf(fmaxf(pt, 1e-7f), 1.f));
                        out[(size_t)b * (11 * N_) + (size_t)s * N_ + p] = loss;
                        float2* pr = (float2*)(out + PRED_OFF + (((size_t)(b * N_ + p)) * 11 + s) * 2);
                        *pr = make_float2(p0, p1);
                        out[NORM_OFF + (size_t)b * (11 * N_) + (size_t)s * N_ + p] = sqrtf(NR[mt][hh]);
                    }
                }
            }
        }
        buf ^= 1;
        // no end-of-tile barrier: next iteration's cpwait0+syncthreads protects buffers
    }
    #undef PREFETCH
}

// ---------------- launch ----------------
extern "C" void kernel_launch(void* const* d_in, const int* in_sizes, int n_in,
                              void* d_out, int out_size) {
    const int*   x    = (const int*)d_in[0];
    const float* y    = (const float*)d_in[1];
    const float* embW = (const float*)d_in[2];
    const float* embb = (const float*)d_in[3];
    const float* lab  = (const float*)d_in[4];
    const float* cnW1 = (const float*)d_in[5];
    const float* cnb1 = (const float*)d_in[6];
    const float* cnW2 = (const float*)d_in[7];
    const float* cnb2 = (const float*)d_in[8];
    const float* bnW1 = (const float*)d_in[9];
    const float* bnb1 = (const float*)d_in[10];
    const float* bnW2 = (const float*)d_in[11];
    const float* bnb2 = (const float*)d_in[12];
    const float* llrW = (const float*)d_in[13];
    const float* llrb = (const float*)d_in[14];
    float* out = (float*)d_out;

    cudaFuncSetAttribute(stage_kernel, cudaFuncAttributeMaxDynamicSharedMemorySize, DSMEM_BYTES);

    prep_kernel<<<1, 256>>>(cnW1, bnW1, cnW2, bnW2, cnb1, bnb1, cnb2, bnb2, lab);
    stage0_kernel<<<(B_ * N_ * 16) / 256, 256>>>(x, y, embW, embb, llrW, llrb, out);
    for (int s = 1; s <= 10; s++) {
        stage_kernel<<<152, 256, DSMEM_BYTES>>>(1 << s, (s - 1) & 1, s, llrW, llrb, out);
    }
}

// round 7
// speedup vs baseline: 1.1715x; 1.1715x over previous
#include <cuda_runtime.h>
#include <cuda_bf16.h>

#define B_ 256
#define N_ 1024
#define NT 1024              // tiles of 128 pairs

#define PRED_OFF (B_*11*N_)                  // 2883584
#define NORM_OFF (PRED_OFF + B_*N_*11*2)     // 8650752

#define SX 136               // bf16 stride for X/H and W1 tiles (272B rows)
#define SW 72                // bf16 stride for W2 tiles (144B rows)

// smem byte offsets
#define OXHI 0
#define OXLO 34816
#define OW1H 69632
#define OW1L 104448
#define OW2  139264          // 4 x 9216: cn_hi, cn_lo, bn_hi, bn_lo
#define OT   176128
#define OB1  176640
#define OB2  177152
#define OLW  177664
#define DSMEM_BYTES 178176

typedef unsigned long long u64;
typedef unsigned int u32;

// ---------------- persistent device scratch ----------------
__device__ __align__(16) float g_e[2][(size_t)B_ * N_ * 64];
__device__ unsigned char g_v[2][B_ * N_];
__device__ __align__(16) __nv_bfloat16 g_W1hi[16384];   // W1T fused [j=128][k=128]
__device__ __align__(16) __nv_bfloat16 g_W1lo[16384];
__device__ __align__(16) __nv_bfloat16 g_W2i[4][4096];  // cn_hi, cn_lo, bn_hi, bn_lo [j=64][k=64]
__device__ float g_B1[128], g_B2[128], g_T[128];

// ---------------- helpers ----------------
__device__ __forceinline__ u32 smem_u32(const void* p) {
    u32 a; asm("{ .reg .u64 t; cvta.to.shared.u64 t, %1; cvt.u32.u64 %0, t; }" : "=r"(a) : "l"(p));
    return a;
}
__device__ __forceinline__ void ldsm4(u32 addr, u32& r0, u32& r1, u32& r2, u32& r3) {
    asm volatile("ldmatrix.sync.aligned.m8n8.x4.shared.b16 {%0,%1,%2,%3}, [%4];"
        : "=r"(r0), "=r"(r1), "=r"(r2), "=r"(r3) : "r"(addr));
}
__device__ __forceinline__ void mma16816(float* c, const u32* a, u32 b0, u32 b1) {
    asm volatile("mma.sync.aligned.m16n8k16.row.col.f32.bf16.bf16.f32 "
        "{%0,%1,%2,%3}, {%4,%5,%6,%7}, {%8,%9}, {%0,%1,%2,%3};"
        : "+f"(c[0]), "+f"(c[1]), "+f"(c[2]), "+f"(c[3])
        : "r"(a[0]), "r"(a[1]), "r"(a[2]), "r"(a[3]), "r"(b0), "r"(b1));
}
__device__ __forceinline__ u32 pkhi(float a, float b, u32& lopk) {
    __nv_bfloat16 ha = __float2bfloat16(a), hb = __float2bfloat16(b);
    __nv_bfloat16 la = __float2bfloat16(a - __bfloat162float(ha));
    __nv_bfloat16 lb = __float2bfloat16(b - __bfloat162float(hb));
    __nv_bfloat162 H = __halves2bfloat162(ha, hb), L = __halves2bfloat162(la, lb);
    lopk = *(u32*)&L;
    return *(u32*)&H;
}

// ---------------- weight preprocessing ----------------
__global__ void prep_kernel(const float* cnW1, const float* bnW1,
                            const float* cnW2, const float* bnW2,
                            const float* cnb1, const float* bnb1,
                            const float* cnb2, const float* bnb2,
                            const float* lab) {
    int t = threadIdx.x;
    for (int i = t; i < 128 * 128; i += 256) {
        int j = i >> 7, k = i & 127;        // [j][k] transposed image
        float a = (j < 64) ? cnW1[k * 64 + j] : bnW1[k * 64 + (j - 64)];
        __nv_bfloat16 h = __float2bfloat16(a);
        g_W1hi[i] = h;
        g_W1lo[i] = __float2bfloat16(a - __bfloat162float(h));
    }
    for (int i = t; i < 4096; i += 256) {
        int j = i >> 6, k = i & 63;
        float a = cnW2[k * 64 + j];
        __nv_bfloat16 h = __float2bfloat16(a);
        g_W2i[0][i] = h;
        g_W2i[1][i] = __float2bfloat16(a - __bfloat162float(h));
        float bnv = bnW2[k * 64 + j];
        __nv_bfloat16 hb = __float2bfloat16(bnv);
        g_W2i[2][i] = hb;
        g_W2i[3][i] = __float2bfloat16(bnv - __bfloat162float(hb));
    }
    if (t < 64) {
        g_B1[t] = cnb1[t]; g_B1[64 + t] = bnb1[t];
        g_B2[t] = cnb2[t]; g_B2[64 + t] = bnb2[t];
    }
    if (t < 128) {
        int v = t >> 6, j = t & 63;
        float s = 0.f;
        for (int m = 0; m < 64; m++) s += lab[v * 64 + m] * bnW1[(128 + m) * 64 + j];
        g_T[t] = s;
    }
}

// ---------------- stage 0: embedding + fused head ----------------
__global__ void stage0_kernel(const int* __restrict__ x, const float* __restrict__ y,
                              const float* __restrict__ embW, const float* __restrict__ embb,
                              const float* __restrict__ llrW, const float* __restrict__ llrb,
                              float* __restrict__ out) {
    int f = blockIdx.x * blockDim.x + threadIdx.x;
    int pos = f >> 4;
    int c4 = (f & 15) << 2;
    float y0 = y[pos * 2 + 0], y1 = y[pos * 2 + 1];
    float4 w0 = *(const float4*)(embW + c4);
    float4 w1 = *(const float4*)(embW + 64 + c4);
    float4 bb = *(const float4*)(embb + c4);
    float4 e;
    e.x = fmaf(y0, w0.x, fmaf(y1, w1.x, bb.x));
    e.y = fmaf(y0, w0.y, fmaf(y1, w1.y, bb.y));
    e.z = fmaf(y0, w0.z, fmaf(y1, w1.z, bb.z));
    e.w = fmaf(y0, w0.w, fmaf(y1, w1.w, bb.w));
    *(float4*)(&g_e[0][(size_t)pos * 64 + c4]) = e;

    float4 wa = *(const float4*)(llrW + c4 * 2);
    float4 wb = *(const float4*)(llrW + c4 * 2 + 4);
    float l0 = e.x * wa.x + e.y * wa.z + e.z * wb.x + e.w * wb.z;
    float l1 = e.x * wa.y + e.y * wa.w + e.z * wb.y + e.w * wb.w;
    float nr = e.x * e.x + e.y * e.y + e.z * e.z + e.w * e.w;
    #pragma unroll
    for (int o = 8; o >= 1; o >>= 1) {
        l0 += __shfl_xor_sync(0xffffffffu, l0, o);
        l1 += __shfl_xor_sync(0xffffffffu, l1, o);
        nr += __shfl_xor_sync(0xffffffffu, nr, o);
    }
    if ((f & 15) == 0) {
        int v = x[pos];
        g_v[0][pos] = (unsigned char)v;
        l0 += llrb[0]; l1 += llrb[1];
        float m = fmaxf(l0, l1);
        float x0 = expf(l0 - m), x1 = expf(l1 - m);
        float inv = 1.f / (x0 + x1);
        float p0 = x0 * inv, p1 = x1 * inv;
        float pt = v ? p1 : p0;
        float loss = -logf(fminf(fmaxf(pt, 1e-7f), 1.f));
        int b = pos >> 10, p = pos & 1023;
        out[(size_t)b * (11 * N_) + p] = loss;
        float2* pr = (float2*)(out + PRED_OFF + (((size_t)(b * N_ + p)) * 11) * 2);
        *pr = make_float2(p0, p1);
        out[NORM_OFF + (size_t)b * (11 * N_) + p] = sqrtf(nr);
    }
}

// ---------------- main butterfly-stage kernel (mma.sync, 16 warps) ----------------
__global__ void __launch_bounds__(512, 1)
stage_kernel(int scope, int src, int s,
             const float* __restrict__ llrW, const float* __restrict__ llrb,
             float* __restrict__ out) {
    extern __shared__ char smp[];
    const u32 smb = smem_u32(smp);
    float* sT  = (float*)(smp + OT);
    float* sB1 = (float*)(smp + OB1);
    float* sB2 = (float*)(smp + OB2);
    float* sLW = (float*)(smp + OLW);
    __shared__ unsigned char sVx[128], sVe[128];

    const int tid = threadIdx.x;

    {   // stage weights: W1 hi/lo and W2 into padded smem layouts
        #pragma unroll
        for (int it = 0; it < 4; it++) {
            int i = tid + it * 512;          // 2048 uint4 per buffer
            int j = i >> 4, c = i & 15;
            uint4 v1 = ((const uint4*)g_W1hi)[i];
            uint4 v2 = ((const uint4*)g_W1lo)[i];
            *(uint4*)(smp + OW1H + j * (SX * 2) + c * 16) = v1;
            *(uint4*)(smp + OW1L + j * (SX * 2) + c * 16) = v2;
            int mt = i >> 9, rem = i & 511;
            int j2 = rem >> 3, c2 = rem & 7;
            uint4 v3 = ((const uint4*)g_W2i)[mt * 512 + j2 * 8 + c2];
            *(uint4*)(smp + OW2 + mt * 9216 + j2 * (SW * 2) + c2 * 16) = v3;
        }
        if (tid < 128) { sT[tid] = g_T[tid]; sB1[tid] = g_B1[tid]; sB2[tid] = g_B2[tid]; sLW[tid] = llrW[tid]; }
    }
    __syncthreads();

    const int half = scope >> 1;
    const int dst = src ^ 1;
    const int w = tid >> 5, l = tid & 32 - 1;
    // GEMM1 grid: 4m x 4n, 32x32 per warp
    const int wm = w & 3, wn = w >> 2;
    const int m0 = wm * 32;
    const int n0 = wn * 32;
    const int side1 = wn >> 1;               // epilogue1 side (cols >= 64?)
    // GEMM2 grid: 8m x 2n, 16 rows x full 64-col side per warp
    const int wm2 = w & 7, side2 = w >> 3;
    const int r0b = wm2 * 16;
    const float lb0 = llrb[0], lb1 = llrb[1];

    // ldmatrix per-thread address components (byte offsets)
    const int aoff  = (m0 + (l & 15)) * (SX * 2) + ((l >> 4) << 3) * 2;          // A frag, GEMM1
    const int boff1 = ((l & 7) + ((l >> 1) & 8) + n0) * (SX * 2) + (l & 8) * 2;  // B frag, GEMM1
    const int aoff2 = (r0b + (l & 15)) * (SX * 2) + (side2 * 64 + ((l >> 4) << 3)) * 2;
    const int boff2 = ((l & 7) + ((l >> 1) & 8)) * (SW * 2) + (l & 8) * 2;
    const u32 w2hiB = smb + OW2 + side2 * 18432;

    for (int tile = blockIdx.x; tile < NT; tile += gridDim.x) {
        int b  = tile >> 2;
        int j0 = (tile & 3) << 7;
        const float* eb = g_e[src] + (size_t)b * (N_ * 64);
        const unsigned char* vb = g_v[src] + b * N_;

        // ---- bits ----
        if (tid < 128) {
            int j = j0 + tid;
            int so = ((j & ~(half - 1)) << 1) | (j & (half - 1));
            unsigned char vo = vb[so], ve = vb[so + half];
            sVx[tid] = (unsigned char)((vo + ve) & 1);
            sVe[tid] = ve;
        }
        // ---- gather X (128 pairs x 128 dims) as bf16 hi/lo ----
        #pragma unroll
        for (int it = 0; it < 4; it++) {
            int c  = tid + (it << 9);
            int r  = c >> 4;
            int f8 = c & 15;
            int hs = f8 >> 3;
            int j  = j0 + r;
            int so = ((j & ~(half - 1)) << 1) | (j & (half - 1));
            const float* p = eb + (size_t)(so + hs * half) * 64 + ((f8 & 7) << 3);
            float4 v0 = *(const float4*)p;
            float4 v1 = *(const float4*)(p + 4);
            uint4 H, L;
            H.x = pkhi(v0.x, v0.y, L.x); H.y = pkhi(v0.z, v0.w, L.y);
            H.z = pkhi(v1.x, v1.y, L.z); H.w = pkhi(v1.z, v1.w, L.w);
            int ad = r * (SX * 2) + f8 * 16;
            *(uint4*)(smp + OXHI + ad) = H;
            *(uint4*)(smp + OXLO + ad) = L;
        }
        __syncthreads();

        // ---- GEMM1: C[128x128] = X @ W1T^T, 3-term bf16 split, 32x32/warp ----
        float acc[2][4][4];
        #pragma unroll
        for (int mt = 0; mt < 2; mt++)
            #pragma unroll
            for (int nt = 0; nt < 4; nt++)
                #pragma unroll
                for (int q = 0; q < 4; q++) acc[mt][nt][q] = 0.f;

        #pragma unroll
        for (int kc = 0; kc < 8; kc++) {
            int kb = kc * 32;
            u32 ah[2][4], al[2][4];
            #pragma unroll
            for (int mt = 0; mt < 2; mt++) {
                ldsm4(smb + OXHI + aoff + mt * 16 * (SX * 2) + kb, ah[mt][0], ah[mt][1], ah[mt][2], ah[mt][3]);
                ldsm4(smb + OXLO + aoff + mt * 16 * (SX * 2) + kb, al[mt][0], al[mt][1], al[mt][2], al[mt][3]);
            }
            #pragma unroll
            for (int np = 0; np < 2; np++) {
                u32 bh[4], bl[4];
                ldsm4(smb + OW1H + boff1 + np * 16 * (SX * 2) + kb, bh[0], bh[1], bh[2], bh[3]);
                ldsm4(smb + OW1L + boff1 + np * 16 * (SX * 2) + kb, bl[0], bl[1], bl[2], bl[3]);
                #pragma unroll
                for (int mt = 0; mt < 2; mt++) {
                    #pragma unroll
                    for (int hh = 0; hh < 2; hh++) {
                        float* c = acc[mt][np * 2 + hh];
                        mma16816(c, ah[mt], bh[2 * hh], bh[2 * hh + 1]);
                        mma16816(c, ah[mt], bl[2 * hh], bl[2 * hh + 1]);
                        mma16816(c, al[mt], bh[2 * hh], bh[2 * hh + 1]);
                    }
                }
            }
        }
        __syncthreads();   // all reads of X done before H overwrites it

        // ---- epilogue1: h = relu(C + b1 + T[vx]) -> H bf16 hi/lo into X buffer ----
        #pragma unroll
        for (int mt = 0; mt < 2; mt++) {
            int rowa = m0 + mt * 16 + (l >> 2);
            int rowb = rowa + 8;
            int va = sVx[rowa], vbt = sVx[rowb];
            #pragma unroll
            for (int nt = 0; nt < 4; nt++) {
                float* c = acc[mt][nt];
                int col = n0 + nt * 8 + (l & 3) * 2;
                float b0 = sB1[col], b1v = sB1[col + 1];
                float v00 = c[0] + b0, v01 = c[1] + b1v;
                float v10 = c[2] + b0, v11 = c[3] + b1v;
                if (side1) {
                    int tcol = col - 64;
                    v00 += sT[va * 64 + tcol];  v01 += sT[va * 64 + tcol + 1];
                    v10 += sT[vbt * 64 + tcol]; v11 += sT[vbt * 64 + tcol + 1];
                }
                v00 = fmaxf(v00, 0.f); v01 = fmaxf(v01, 0.f);
                v10 = fmaxf(v10, 0.f); v11 = fmaxf(v11, 0.f);
                u32 lo0, lo1;
                u32 hi0 = pkhi(v00, v01, lo0);
                u32 hi1 = pkhi(v10, v11, lo1);
                int ada = rowa * (SX * 2) + col * 2;
                int adb = rowb * (SX * 2) + col * 2;
                *(u32*)(smp + OXHI + ada) = hi0;
                *(u32*)(smp + OXLO + ada) = lo0;
                *(u32*)(smp + OXHI + adb) = hi1;
                *(u32*)(smp + OXLO + adb) = lo1;
            }
        }
        __syncthreads();

        // ---- GEMM2: per side [128x64] = H_side @ W2_side; warp = 16 rows x 64 cols ----
        float acc2[8][4];
        #pragma unroll
        for (int nt = 0; nt < 8; nt++)
            #pragma unroll
            for (int q = 0; q < 4; q++) acc2[nt][q] = 0.f;

        #pragma unroll
        for (int kc = 0; kc < 4; kc++) {
            int kb = kc * 32;
            u32 ah[4], al[4];
            ldsm4(smb + OXHI + aoff2 + kb, ah[0], ah[1], ah[2], ah[3]);
            ldsm4(smb + OXLO + aoff2 + kb, al[0], al[1], al[2], al[3]);
            #pragma unroll
            for (int np = 0; np < 4; np++) {
                u32 bh[4], bl[4];
                ldsm4(w2hiB + boff2 + np * 16 * (SW * 2) + kb, bh[0], bh[1], bh[2], bh[3]);
                ldsm4(w2hiB + 9216 + boff2 + np * 16 * (SW * 2) + kb, bl[0], bl[1], bl[2], bl[3]);
                #pragma unroll
                for (int hh = 0; hh < 2; hh++) {
                    float* c = acc2[np * 2 + hh];
                    mma16816(c, ah, bh[2 * hh], bh[2 * hh + 1]);
                    mma16816(c, ah, bl[2 * hh], bl[2 * hh + 1]);
                    mma16816(c, al, bh[2 * hh], bh[2 * hh + 1]);
                }
            }
        }

        // ---- epilogue2: bias + e' store + fused head (rows r0b..r0b+15, side2) ----
        {
            float L0[2] = {0.f, 0.f}, L1[2] = {0.f, 0.f}, NR[2] = {0.f, 0.f};
            int rowa = r0b + (l >> 2);
            int pa = ((j0 + rowa) << 1) | side2;
            int pb = ((j0 + rowa + 8) << 1) | side2;
            float* ea  = g_e[dst] + ((size_t)b * N_ + pa) * 64;
            float* ebp = g_e[dst] + ((size_t)b * N_ + pb) * 64;
            #pragma unroll
            for (int nt = 0; nt < 8; nt++) {
                float* c = acc2[nt];
                int col = nt * 8 + (l & 3) * 2;          // 0..63 output dim
                float b0 = sB2[side2 * 64 + col], b1v = sB2[side2 * 64 + col + 1];
                float o00 = c[0] + b0, o01 = c[1] + b1v;
                float o10 = c[2] + b0, o11 = c[3] + b1v;
                *(float2*)(ea + col)  = make_float2(o00, o01);
                *(float2*)(ebp + col) = make_float2(o10, o11);
                float w0 = sLW[col * 2], w1 = sLW[col * 2 + 1];
                float w2 = sLW[col * 2 + 2], w3 = sLW[col * 2 + 3];
                L0[0] += o00 * w0 + o01 * w2;
                L1[0] += o00 * w1 + o01 * w3;
                NR[0] += o00 * o00 + o01 * o01;
                L0[1] += o10 * w0 + o11 * w2;
                L1[1] += o10 * w1 + o11 * w3;
                NR[1] += o10 * o10 + o11 * o11;
            }
            #pragma unroll
            for (int off = 2; off >= 1; off >>= 1) {
                #pragma unroll
                for (int hh = 0; hh < 2; hh++) {
                    L0[hh] += __shfl_xor_sync(0xffffffffu, L0[hh], off);
                    L1[hh] += __shfl_xor_sync(0xffffffffu, L1[hh], off);
                    NR[hh] += __shfl_xor_sync(0xffffffffu, NR[hh], off);
                }
            }
            if ((l & 3) == 0) {
                #pragma unroll
                for (int hh = 0; hh < 2; hh++) {
                    int r = r0b + (l >> 2) + hh * 8;
                    int p = ((j0 + r) << 1) | side2;
                    unsigned char vp = side2 ? sVe[r] : sVx[r];
                    g_v[dst][b * N_ + p] = vp;
                    float l0 = L0[hh] + lb0, l1 = L1[hh] + lb1;
                    float mm = fmaxf(l0, l1);
                    float x0 = expf(l0 - mm), x1 = expf(l1 - mm);
                    float inv = 1.f / (x0 + x1);
                    float p0 = x0 * inv, p1 = x1 * inv;
                    float pt = vp ? p1 : p0;
                    float loss = -logf(fminf(fmaxf(pt, 1e-7f), 1.f));
                    out[(size_t)b * (11 * N_) + (size_t)s * N_ + p] = loss;
                    float2* pr = (float2*)(out + PRED_OFF + (((size_t)(b * N_ + p)) * 11 + s) * 2);
                    *pr = make_float2(p0, p1);
                    out[NORM_OFF + (size_t)b * (11 * N_) + (size_t)s * N_ + p] = sqrtf(NR[hh]);
                }
            }
        }
        __syncthreads();   // protect H buffer + bits before next tile
    }
}

// ---------------- launch ----------------
extern "C" void kernel_launch(void* const* d_in, const int* in_sizes, int n_in,
                              void* d_out, int out_size) {
    const int*   x    = (const int*)d_in[0];
    const float* y    = (const float*)d_in[1];
    const float* embW = (const float*)d_in[2];
    const float* embb = (const float*)d_in[3];
    const float* lab  = (const float*)d_in[4];
    const float* cnW1 = (const float*)d_in[5];
    const float* cnb1 = (const float*)d_in[6];
    const float* cnW2 = (const float*)d_in[7];
    const float* cnb2 = (const float*)d_in[8];
    const float* bnW1 = (const float*)d_in[9];
    const float* bnb1 = (const float*)d_in[10];
    const float* bnW2 = (const float*)d_in[11];
    const float* bnb2 = (const float*)d_in[12];
    const float* llrW = (const float*)d_in[13];
    const float* llrb = (const float*)d_in[14];
    float* out = (float*)d_out;

    cudaFuncSetAttribute(stage_kernel, cudaFuncAttributeMaxDynamicSharedMemorySize, DSMEM_BYTES);

    prep_kernel<<<1, 256>>>(cnW1, bnW1, cnW2, bnW2, cnb1, bnb1, cnb2, bnb2, lab);
    stage0_kernel<<<(B_ * N_ * 16) / 256, 256>>>(x, y, embW, embb, llrW, llrb, out);
    for (int s = 1; s <= 10; s++) {
        stage_kernel<<<152, 512, DSMEM_BYTES>>>(1 << s, (s - 1) & 1, s, llrW, llrb, out);
    }
}

// round 8
// speedup vs baseline: 1.2305x; 1.0504x over previous
#include <cuda_runtime.h>
#include <cuda_bf16.h>

#define B_ 256
#define N_ 1024
#define NT2 2048             // tiles of 64 pairs

#define PRED_OFF (B_*11*N_)                  // 2883584
#define NORM_OFF (PRED_OFF + B_*N_*11*2)     // 8650752

// X/H tiles: 64 rows x 272B (SX=136 bf16), hi+lo per half
#define XHALF 34816          // per-half X block (hi 17408 | lo 17408)
#define OW1H 69632           // W1T hi: 128 rows x 272B
#define OW1L 104448
#define OW2  139264          // 4 x 9216: cn_hi, cn_lo, bn_hi, bn_lo (rows of 144B)
#define OT   176128
#define OB1  176640
#define OB2  177152
#define OLW  177664
#define DSMEM_BYTES 178176

typedef unsigned long long u64;
typedef unsigned int u32;

// ---------------- persistent device scratch ----------------
__device__ __align__(16) float g_e[2][(size_t)B_ * N_ * 64];
__device__ unsigned char g_v[2][B_ * N_];
__device__ __align__(16) __nv_bfloat16 g_W1hi[16384];   // W1T fused [j=128][k=128]
__device__ __align__(16) __nv_bfloat16 g_W1lo[16384];
__device__ __align__(16) __nv_bfloat16 g_W2i[4][4096];  // cn_hi, cn_lo, bn_hi, bn_lo [j=64][k=64]
__device__ float g_B1[128], g_B2[128], g_T[128];

// ---------------- helpers ----------------
__device__ __forceinline__ u32 smem_u32(const void* p) {
    u32 a; asm("{ .reg .u64 t; cvta.to.shared.u64 t, %1; cvt.u32.u64 %0, t; }" : "=r"(a) : "l"(p));
    return a;
}
__device__ __forceinline__ void ldsm4(u32 addr, u32& r0, u32& r1, u32& r2, u32& r3) {
    asm volatile("ldmatrix.sync.aligned.m8n8.x4.shared.b16 {%0,%1,%2,%3}, [%4];"
        : "=r"(r0), "=r"(r1), "=r"(r2), "=r"(r3) : "r"(addr));
}
__device__ __forceinline__ void mma16816(float* c, const u32* a, u32 b0, u32 b1) {
    asm volatile("mma.sync.aligned.m16n8k16.row.col.f32.bf16.bf16.f32 "
        "{%0,%1,%2,%3}, {%4,%5,%6,%7}, {%8,%9}, {%0,%1,%2,%3};"
        : "+f"(c[0]), "+f"(c[1]), "+f"(c[2]), "+f"(c[3])
        : "r"(a[0]), "r"(a[1]), "r"(a[2]), "r"(a[3]), "r"(b0), "r"(b1));
}
__device__ __forceinline__ u32 pkhi(float a, float b, u32& lopk) {
    __nv_bfloat16 ha = __float2bfloat16(a), hb = __float2bfloat16(b);
    __nv_bfloat16 la = __float2bfloat16(a - __bfloat162float(ha));
    __nv_bfloat16 lb = __float2bfloat16(b - __bfloat162float(hb));
    __nv_bfloat162 H = __halves2bfloat162(ha, hb), L = __halves2bfloat162(la, lb);
    lopk = *(u32*)&L;
    return *(u32*)&H;
}

// ---------------- weight preprocessing ----------------
__global__ void prep_kernel(const float* cnW1, const float* bnW1,
                            const float* cnW2, const float* bnW2,
                            const float* cnb1, const float* bnb1,
                            const float* cnb2, const float* bnb2,
                            const float* lab) {
    int t = threadIdx.x;
    for (int i = t; i < 128 * 128; i += 256) {
        int j = i >> 7, k = i & 127;        // [j][k] transposed image
        float a = (j < 64) ? cnW1[k * 64 + j] : bnW1[k * 64 + (j - 64)];
        __nv_bfloat16 h = __float2bfloat16(a);
        g_W1hi[i] = h;
        g_W1lo[i] = __float2bfloat16(a - __bfloat162float(h));
    }
    for (int i = t; i < 4096; i += 256) {
        int j = i >> 6, k = i & 63;
        float a = cnW2[k * 64 + j];
        __nv_bfloat16 h = __float2bfloat16(a);
        g_W2i[0][i] = h;
        g_W2i[1][i] = __float2bfloat16(a - __bfloat162float(h));
        float bnv = bnW2[k * 64 + j];
        __nv_bfloat16 hb = __float2bfloat16(bnv);
        g_W2i[2][i] = hb;
        g_W2i[3][i] = __float2bfloat16(bnv - __bfloat162float(hb));
    }
    if (t < 64) {
        g_B1[t] = cnb1[t]; g_B1[64 + t] = bnb1[t];
        g_B2[t] = cnb2[t]; g_B2[64 + t] = bnb2[t];
    }
    if (t < 128) {
        int v = t >> 6, j = t & 63;
        float s = 0.f;
        for (int m = 0; m < 64; m++) s += lab[v * 64 + m] * bnW1[(128 + m) * 64 + j];
        g_T[t] = s;
    }
}

// ---------------- stage 0: embedding + fused head ----------------
__global__ void stage0_kernel(const int* __restrict__ x, const float* __restrict__ y,
                              const float* __restrict__ embW, const float* __restrict__ embb,
                              const float* __restrict__ llrW, const float* __restrict__ llrb,
                              float* __restrict__ out) {
    int f = blockIdx.x * blockDim.x + threadIdx.x;
    int pos = f >> 4;
    int c4 = (f & 15) << 2;
    float y0 = y[pos * 2 + 0], y1 = y[pos * 2 + 1];
    float4 w0 = *(const float4*)(embW + c4);
    float4 w1 = *(const float4*)(embW + 64 + c4);
    float4 bb = *(const float4*)(embb + c4);
    float4 e;
    e.x = fmaf(y0, w0.x, fmaf(y1, w1.x, bb.x));
    e.y = fmaf(y0, w0.y, fmaf(y1, w1.y, bb.y));
    e.z = fmaf(y0, w0.z, fmaf(y1, w1.z, bb.z));
    e.w = fmaf(y0, w0.w, fmaf(y1, w1.w, bb.w));
    *(float4*)(&g_e[0][(size_t)pos * 64 + c4]) = e;

    float4 wa = *(const float4*)(llrW + c4 * 2);
    float4 wb = *(const float4*)(llrW + c4 * 2 + 4);
    float l0 = e.x * wa.x + e.y * wa.z + e.z * wb.x + e.w * wb.z;
    float l1 = e.x * wa.y + e.y * wa.w + e.z * wb.y + e.w * wb.w;
    float nr = e.x * e.x + e.y * e.y + e.z * e.z + e.w * e.w;
    #pragma unroll
    for (int o = 8; o >= 1; o >>= 1) {
        l0 += __shfl_xor_sync(0xffffffffu, l0, o);
        l1 += __shfl_xor_sync(0xffffffffu, l1, o);
        nr += __shfl_xor_sync(0xffffffffu, nr, o);
    }
    if ((f & 15) == 0) {
        int v = x[pos];
        g_v[0][pos] = (unsigned char)v;
        l0 += llrb[0]; l1 += llrb[1];
        float m = fmaxf(l0, l1);
        float x0 = expf(l0 - m), x1 = expf(l1 - m);
        float inv = 1.f / (x0 + x1);
        float p0 = x0 * inv, p1 = x1 * inv;
        float pt = v ? p1 : p0;
        float loss = -logf(fminf(fmaxf(pt, 1e-7f), 1.f));
        int b = pos >> 10, p = pos & 1023;
        out[(size_t)b * (11 * N_) + p] = loss;
        float2* pr = (float2*)(out + PRED_OFF + (((size_t)(b * N_ + p)) * 11) * 2);
        *pr = make_float2(p0, p1);
        out[NORM_OFF + (size_t)b * (11 * N_) + p] = sqrtf(nr);
    }
}

// ---------------- main butterfly-stage kernel: 2 independent 8-warp pipelines ----------------
__global__ void __launch_bounds__(512, 1)
stage_kernel(int scope, int src, int s,
             const float* __restrict__ llrW, const float* __restrict__ llrb,
             float* __restrict__ out) {
    extern __shared__ char smp[];
    const u32 smb = smem_u32(smp);
    float* sT  = (float*)(smp + OT);
    float* sB1 = (float*)(smp + OB1);
    float* sB2 = (float*)(smp + OB2);
    float* sLW = (float*)(smp + OLW);
    __shared__ unsigned char sVx[2][64], sVe[2][64];

    const int tid = threadIdx.x;

    {   // stage weights: W1 hi/lo (272B rows) and W2 (144B rows) into smem
        #pragma unroll
        for (int it = 0; it < 4; it++) {
            int i = tid + it * 512;          // 2048 uint4 per buffer
            int j = i >> 4, c = i & 15;
            uint4 v1 = ((const uint4*)g_W1hi)[i];
            uint4 v2 = ((const uint4*)g_W1lo)[i];
            *(uint4*)(smp + OW1H + j * 272 + c * 16) = v1;
            *(uint4*)(smp + OW1L + j * 272 + c * 16) = v2;
            int mt = i >> 9, rem = i & 511;
            int j2 = rem >> 3, c2 = rem & 7;
            uint4 v3 = ((const uint4*)g_W2i)[mt * 512 + j2 * 8 + c2];
            *(uint4*)(smp + OW2 + mt * 9216 + j2 * 144 + c2 * 16) = v3;
        }
        if (tid < 128) { sT[tid] = g_T[tid]; sB1[tid] = g_B1[tid]; sB2[tid] = g_B2[tid]; sLW[tid] = llrW[tid]; }
    }
    __syncthreads();

    const int hsc = scope >> 1;              // half-scope
    const int dst = src ^ 1;
    const int hid = tid >> 8;                // pipeline half 0/1
    const int lt  = tid & 255;               // thread within half
    const int w = lt >> 5, l = lt & 31;      // local warp 0..7, lane
    const int hbar = 1 + hid;

    // GEMM1 grid (per half): 2m x 4n, 32x32 per warp over [64 x 128]
    const int wm = w & 1, wn = w >> 1;
    const int m0 = wm * 32;
    const int n0 = wn * 32;
    const int side1 = wn >> 1;
    // GEMM2 grid: 4m x 2n, 16 rows x 64-col side per warp
    const int wm2 = w & 3, side2 = w >> 2;
    const int r0b = wm2 * 16;
    const float lb0 = llrb[0], lb1 = llrb[1];

    const u32 xb  = smb + hid * XHALF;       // X hi (64 x 272B)
    const u32 xbl = xb + 17408;              // X lo
    char* xbp  = smp + hid * XHALF;
    char* xblp = xbp + 17408;

    // ldmatrix per-thread components (byte offsets)
    const int aoff  = (m0 + (l & 15)) * 272 + ((l >> 4) << 3) * 2;
    const int boff1 = ((l & 7) + ((l >> 1) & 8) + n0) * 272 + (l & 8) * 2;
    const int aoff2 = (r0b + (l & 15)) * 272 + (side2 * 64 + ((l >> 4) << 3)) * 2;
    const int boff2 = ((l & 7) + ((l >> 1) & 8)) * 144 + (l & 8) * 2;
    const u32 w2hiB = smb + OW2 + side2 * 18432;

    #define HBAR() asm volatile("bar.sync %0, 256;" :: "r"(hbar) : "memory")

    for (int tile = blockIdx.x * 2 + hid; tile < NT2; tile += 304) {
        int b  = tile >> 3;
        int j0 = (tile & 7) << 6;            // 64-pair tile base within batch
        const float* eb = g_e[src] + (size_t)b * (N_ * 64);
        const unsigned char* vb = g_v[src] + b * N_;

        // ---- bits ----
        if (lt < 64) {
            int j = j0 + lt;
            int so = ((j & ~(hsc - 1)) << 1) | (j & (hsc - 1));
            unsigned char vo = vb[so], ve = vb[so + hsc];
            sVx[hid][lt] = (unsigned char)((vo + ve) & 1);
            sVe[hid][lt] = ve;
        }
        // ---- gather X (64 pairs x 128 dims) as bf16 hi/lo ----
        #pragma unroll
        for (int it = 0; it < 4; it++) {
            int c  = lt + (it << 8);         // 0..1023
            int r  = c >> 4;
            int f8 = c & 15;
            int hs = f8 >> 3;
            int j  = j0 + r;
            int so = ((j & ~(hsc - 1)) << 1) | (j & (hsc - 1));
            const float* p = eb + (size_t)(so + hs * hsc) * 64 + ((f8 & 7) << 3);
            float4 v0 = *(const float4*)p;
            float4 v1 = *(const float4*)(p + 4);
            uint4 H, L;
            H.x = pkhi(v0.x, v0.y, L.x); H.y = pkhi(v0.z, v0.w, L.y);
            H.z = pkhi(v1.x, v1.y, L.z); H.w = pkhi(v1.z, v1.w, L.w);
            int ad = r * 272 + f8 * 16;
            *(uint4*)(xbp + ad)  = H;
            *(uint4*)(xblp + ad) = L;
        }
        HBAR();

        // ---- GEMM1: C[64x128] = X @ W1T^T, 3-term bf16 split, 32x32/warp ----
        float acc[2][4][4];
        #pragma unroll
        for (int mt = 0; mt < 2; mt++)
            #pragma unroll
            for (int nt = 0; nt < 4; nt++)
                #pragma unroll
                for (int q = 0; q < 4; q++) acc[mt][nt][q] = 0.f;

        #pragma unroll
        for (int kc = 0; kc < 8; kc++) {
            int kb = kc * 32;
            u32 ah[2][4], al[2][4];
            #pragma unroll
            for (int mt = 0; mt < 2; mt++) {
                ldsm4(xb + aoff + mt * 16 * 272 + kb,  ah[mt][0], ah[mt][1], ah[mt][2], ah[mt][3]);
                ldsm4(xbl + aoff + mt * 16 * 272 + kb, al[mt][0], al[mt][1], al[mt][2], al[mt][3]);
            }
            #pragma unroll
            for (int np = 0; np < 2; np++) {
                u32 bh[4], bl[4];
                ldsm4(smb + OW1H + boff1 + np * 16 * 272 + kb, bh[0], bh[1], bh[2], bh[3]);
                ldsm4(smb + OW1L + boff1 + np * 16 * 272 + kb, bl[0], bl[1], bl[2], bl[3]);
                #pragma unroll
                for (int mt = 0; mt < 2; mt++) {
                    #pragma unroll
                    for (int hh = 0; hh < 2; hh++) {
                        float* c = acc[mt][np * 2 + hh];
                        mma16816(c, ah[mt], bh[2 * hh], bh[2 * hh + 1]);
                        mma16816(c, ah[mt], bl[2 * hh], bl[2 * hh + 1]);
                        mma16816(c, al[mt], bh[2 * hh], bh[2 * hh + 1]);
                    }
                }
            }
        }
        HBAR();   // all reads of X done before H overwrites it

        // ---- epilogue1: h = relu(C + b1 + T[vx]) -> H bf16 hi/lo into X buffer ----
        #pragma unroll
        for (int mt = 0; mt < 2; mt++) {
            int rowa = m0 + mt * 16 + (l >> 2);
            int rowb = rowa + 8;
            int va = sVx[hid][rowa], vbt = sVx[hid][rowb];
            #pragma unroll
            for (int nt = 0; nt < 4; nt++) {
                float* c = acc[mt][nt];
                int col = n0 + nt * 8 + (l & 3) * 2;
                float b0 = sB1[col], b1v = sB1[col + 1];
                float v00 = c[0] + b0, v01 = c[1] + b1v;
                float v10 = c[2] + b0, v11 = c[3] + b1v;
                if (side1) {
                    int tcol = col - 64;
                    v00 += sT[va * 64 + tcol];  v01 += sT[va * 64 + tcol + 1];
                    v10 += sT[vbt * 64 + tcol]; v11 += sT[vbt * 64 + tcol + 1];
                }
                v00 = fmaxf(v00, 0.f); v01 = fmaxf(v01, 0.f);
                v10 = fmaxf(v10, 0.f); v11 = fmaxf(v11, 0.f);
                u32 lo0, lo1;
                u32 hi0 = pkhi(v00, v01, lo0);
                u32 hi1 = pkhi(v10, v11, lo1);
                int ada = rowa * 272 + col * 2;
                int adb = rowb * 272 + col * 2;
                *(u32*)(xbp + ada)  = hi0;
                *(u32*)(xblp + ada) = lo0;
                *(u32*)(xbp + adb)  = hi1;
                *(u32*)(xblp + adb) = lo1;
            }
        }
        HBAR();

        // ---- GEMM2: per side [64x64] = H_side @ W2_side; warp = 16 rows x 64 cols ----
        float acc2[8][4];
        #pragma unroll
        for (int nt = 0; nt < 8; nt++)
            #pragma unroll
            for (int q = 0; q < 4; q++) acc2[nt][q] = 0.f;

        #pragma unroll
        for (int kc = 0; kc < 4; kc++) {
            int kb = kc * 32;
            u32 ah[4], al[4];
            ldsm4(xb + aoff2 + kb,  ah[0], ah[1], ah[2], ah[3]);
            ldsm4(xbl + aoff2 + kb, al[0], al[1], al[2], al[3]);
            #pragma unroll
            for (int np = 0; np < 4; np++) {
                u32 bh[4], bl[4];
                ldsm4(w2hiB + boff2 + np * 16 * 144 + kb, bh[0], bh[1], bh[2], bh[3]);
                ldsm4(w2hiB + 9216 + boff2 + np * 16 * 144 + kb, bl[0], bl[1], bl[2], bl[3]);
                #pragma unroll
                for (int hh = 0; hh < 2; hh++) {
                    float* c = acc2[np * 2 + hh];
                    mma16816(c, ah, bh[2 * hh], bh[2 * hh + 1]);
                    mma16816(c, ah, bl[2 * hh], bl[2 * hh + 1]);
                    mma16816(c, al, bh[2 * hh], bh[2 * hh + 1]);
                }
            }
        }

        // ---- epilogue2: bias + e' store + fused head ----
        {
            float L0[2] = {0.f, 0.f}, L1[2] = {0.f, 0.f}, NR[2] = {0.f, 0.f};
            int rowa = r0b + (l >> 2);
            int pa = ((j0 + rowa) << 1) | side2;
            int pb = ((j0 + rowa + 8) << 1) | side2;
            float* ea  = g_e[dst] + ((size_t)b * N_ + pa) * 64;
            float* ebp = g_e[dst] + ((size_t)b * N_ + pb) * 64;
            #pragma unroll
            for (int nt = 0; nt < 8; nt++) {
                float* c = acc2[nt];
                int col = nt * 8 + (l & 3) * 2;
                float b0 = sB2[side2 * 64 + col], b1v = sB2[side2 * 64 + col + 1];
                float o00 = c[0] + b0, o01 = c[1] + b1v;
                float o10 = c[2] + b0, o11 = c[3] + b1v;
                *(float2*)(ea + col)  = make_float2(o00, o01);
                *(float2*)(ebp + col) = make_float2(o10, o11);
                float w0 = sLW[col * 2], w1 = sLW[col * 2 + 1];
                float w2 = sLW[col * 2 + 2], w3 = sLW[col * 2 + 3];
                L0[0] += o00 * w0 + o01 * w2;
                L1[0] += o00 * w1 + o01 * w3;
                NR[0] += o00 * o00 + o01 * o01;
                L0[1] += o10 * w0 + o11 * w2;
                L1[1] += o10 * w1 + o11 * w3;
                NR[1] += o10 * o10 + o11 * o11;
            }
            #pragma unroll
            for (int off = 2; off >= 1; off >>= 1) {
                #pragma unroll
                for (int hh = 0; hh < 2; hh++) {
                    L0[hh] += __shfl_xor_sync(0xffffffffu, L0[hh], off);
                    L1[hh] += __shfl_xor_sync(0xffffffffu, L1[hh], off);
                    NR[hh] += __shfl_xor_sync(0xffffffffu, NR[hh], off);
                }
            }
            if ((l & 3) == 0) {
                #pragma unroll
                for (int hh = 0; hh < 2; hh++) {
                    int r = r0b + (l >> 2) + hh * 8;
                    int p = ((j0 + r) << 1) | side2;
                    unsigned char vp = side2 ? sVe[hid][r] : sVx[hid][r];
                    g_v[dst][b * N_ + p] = vp;
                    float l0 = L0[hh] + lb0, l1 = L1[hh] + lb1;
                    float mm = fmaxf(l0, l1);
                    float x0 = expf(l0 - mm), x1 = expf(l1 - mm);
                    float inv = 1.f / (x0 + x1);
                    float p0 = x0 * inv, p1 = x1 * inv;
                    float pt = vp ? p1 : p0;
                    float loss = -logf(fminf(fmaxf(pt, 1e-7f), 1.f));
                    out[(size_t)b * (11 * N_) + (size_t)s * N_ + p] = loss;
                    float2* pr = (float2*)(out + PRED_OFF + (((size_t)(b * N_ + p)) * 11 + s) * 2);
                    *pr = make_float2(p0, p1);
                    out[NORM_OFF + (size_t)b * (11 * N_) + (size_t)s * N_ + p] = sqrtf(NR[hh]);
                }
            }
        }
        HBAR();   // protect X buffer + bits before next tile
    }
    #undef HBAR
}

// ---------------- launch ----------------
extern "C" void kernel_launch(void* const* d_in, const int* in_sizes, int n_in,
                              void* d_out, int out_size) {
    const int*   x    = (const int*)d_in[0];
    const float* y    = (const float*)d_in[1];
    const float* embW = (const float*)d_in[2];
    const float* embb = (const float*)d_in[3];
    const float* lab  = (const float*)d_in[4];
    const float* cnW1 = (const float*)d_in[5];
    const float* cnb1 = (const float*)d_in[6];
    const float* cnW2 = (const float*)d_in[7];
    const float* cnb2 = (const float*)d_in[8];
    const float* bnW1 = (const float*)d_in[9];
    const float* bnb1 = (const float*)d_in[10];
    const float* bnW2 = (const float*)d_in[11];
    const float* bnb2 = (const float*)d_in[12];
    const float* llrW = (const float*)d_in[13];
    const float* llrb = (const float*)d_in[14];
    float* out = (float*)d_out;

    cudaFuncSetAttribute(stage_kernel, cudaFuncAttributeMaxDynamicSharedMemorySize, DSMEM_BYTES);

    prep_kernel<<<1, 256>>>(cnW1, bnW1, cnW2, bnW2, cnb1, bnb1, cnb2, bnb2, lab);
    stage0_kernel<<<(B_ * N_ * 16) / 256, 256>>>(x, y, embW, embb, llrW, llrb, out);
    for (int s = 1; s <= 10; s++) {
        stage_kernel<<<152, 512, DSMEM_BYTES>>>(1 << s, (s - 1) & 1, s, llrW, llrb, out);
    }
}

// round 10
// speedup vs baseline: 1.3436x; 1.0919x over previous
#include <cuda_runtime.h>
#include <cuda_bf16.h>

#define B_ 256
#define N_ 1024
#define NT4 4096             // tiles of 32 pairs

#define PRED_OFF (B_*11*N_)                  // 2883584
#define NORM_OFF (PRED_OFF + B_*N_*11*2)     // 8650752

// X/H tiles: 32 rows x 272B, hi+lo, per pipeline
#define XPIPE 17408          // per-pipeline X block (hi 8704 | lo 8704)
#define OW1H 69632           // W1T hi: 128 rows x 272B
#define OW1L 104448
#define OW2  139264          // 4 x 9216: cn_hi, cn_lo, bn_hi, bn_lo (rows of 144B)
#define OT   176128
#define OB1  176640
#define OB2  177152
#define OLW  177664
#define DSMEM_BYTES 178176

typedef unsigned long long u64;
typedef unsigned int u32;

// ---------------- persistent device scratch ----------------
__device__ __align__(16) float g_e[2][(size_t)B_ * N_ * 64];
__device__ unsigned char g_v[2][B_ * N_];
__device__ __align__(16) __nv_bfloat16 g_W1hi[16384];   // W1T fused [j=128][k=128]
__device__ __align__(16) __nv_bfloat16 g_W1lo[16384];
__device__ __align__(16) __nv_bfloat16 g_W2i[4][4096];  // cn_hi, cn_lo, bn_hi, bn_lo [j=64][k=64]
__device__ float g_B1[128], g_B2[128], g_T[128];

// ---------------- helpers ----------------
__device__ __forceinline__ u32 smem_u32(const void* p) {
    u32 a; asm("{ .reg .u64 t; cvta.to.shared.u64 t, %1; cvt.u32.u64 %0, t; }" : "=r"(a) : "l"(p));
    return a;
}
__device__ __forceinline__ void ldsm4(u32 addr, u32& r0, u32& r1, u32& r2, u32& r3) {
    asm volatile("ldmatrix.sync.aligned.m8n8.x4.shared.b16 {%0,%1,%2,%3}, [%4];"
        : "=r"(r0), "=r"(r1), "=r"(r2), "=r"(r3) : "r"(addr));
}
__device__ __forceinline__ void stsm4(u32 addr, u32 r0, u32 r1, u32 r2, u32 r3) {
    asm volatile("stmatrix.sync.aligned.m8n8.x4.shared.b16 [%0], {%1,%2,%3,%4};"
        :: "r"(addr), "r"(r0), "r"(r1), "r"(r2), "r"(r3) : "memory");
}
__device__ __forceinline__ void mma16816(float* c, const u32* a, u32 b0, u32 b1) {
    asm volatile("mma.sync.aligned.m16n8k16.row.col.f32.bf16.bf16.f32 "
        "{%0,%1,%2,%3}, {%4,%5,%6,%7}, {%8,%9}, {%0,%1,%2,%3};"
        : "+f"(c[0]), "+f"(c[1]), "+f"(c[2]), "+f"(c[3])
        : "r"(a[0]), "r"(a[1]), "r"(a[2]), "r"(a[3]), "r"(b0), "r"(b1));
}
__device__ __forceinline__ u32 pkhi(float a, float b, u32& lopk) {
    __nv_bfloat16 ha = __float2bfloat16(a), hb = __float2bfloat16(b);
    __nv_bfloat16 la = __float2bfloat16(a - __bfloat162float(ha));
    __nv_bfloat16 lb = __float2bfloat16(b - __bfloat162float(hb));
    __nv_bfloat162 H = __halves2bfloat162(ha, hb), L = __halves2bfloat162(la, lb);
    lopk = *(u32*)&L;
    return *(u32*)&H;
}

// ---------------- weight preprocessing ----------------
__global__ void prep_kernel(const float* cnW1, const float* bnW1,
                            const float* cnW2, const float* bnW2,
                            const float* cnb1, const float* bnb1,
                            const float* cnb2, const float* bnb2,
                            const float* lab) {
    int t = threadIdx.x;
    for (int i = t; i < 128 * 128; i += 256) {
        int j = i >> 7, k = i & 127;        // [j][k] transposed image
        float a = (j < 64) ? cnW1[k * 64 + j] : bnW1[k * 64 + (j - 64)];
        __nv_bfloat16 h = __float2bfloat16(a);
        g_W1hi[i] = h;
        g_W1lo[i] = __float2bfloat16(a - __bfloat162float(h));
    }
    for (int i = t; i < 4096; i += 256) {
        int j = i >> 6, k = i & 63;
        float a = cnW2[k * 64 + j];
        __nv_bfloat16 h = __float2bfloat16(a);
        g_W2i[0][i] = h;
        g_W2i[1][i] = __float2bfloat16(a - __bfloat162float(h));
        float bnv = bnW2[k * 64 + j];
        __nv_bfloat16 hb = __float2bfloat16(bnv);
        g_W2i[2][i] = hb;
        g_W2i[3][i] = __float2bfloat16(bnv - __bfloat162float(hb));
    }
    if (t < 64) {
        g_B1[t] = cnb1[t]; g_B1[64 + t] = bnb1[t];
        g_B2[t] = cnb2[t]; g_B2[64 + t] = bnb2[t];
    }
    if (t < 128) {
        int v = t >> 6, j = t & 63;
        float s = 0.f;
        for (int m = 0; m < 64; m++) s += lab[v * 64 + m] * bnW1[(128 + m) * 64 + j];
        g_T[t] = s;
    }
}

// ---------------- stage 0: embedding + fused head ----------------
__global__ void stage0_kernel(const int* __restrict__ x, const float* __restrict__ y,
                              const float* __restrict__ embW, const float* __restrict__ embb,
                              const float* __restrict__ llrW, const float* __restrict__ llrb,
                              float* __restrict__ out) {
    int f = blockIdx.x * blockDim.x + threadIdx.x;
    int pos = f >> 4;
    int c4 = (f & 15) << 2;
    float y0 = y[pos * 2 + 0], y1 = y[pos * 2 + 1];
    float4 w0 = *(const float4*)(embW + c4);
    float4 w1 = *(const float4*)(embW + 64 + c4);
    float4 bb = *(const float4*)(embb + c4);
    float4 e;
    e.x = fmaf(y0, w0.x, fmaf(y1, w1.x, bb.x));
    e.y = fmaf(y0, w0.y, fmaf(y1, w1.y, bb.y));
    e.z = fmaf(y0, w0.z, fmaf(y1, w1.z, bb.z));
    e.w = fmaf(y0, w0.w, fmaf(y1, w1.w, bb.w));
    *(float4*)(&g_e[0][(size_t)pos * 64 + c4]) = e;

    float4 wa = *(const float4*)(llrW + c4 * 2);
    float4 wb = *(const float4*)(llrW + c4 * 2 + 4);
    float l0 = e.x * wa.x + e.y * wa.z + e.z * wb.x + e.w * wb.z;
    float l1 = e.x * wa.y + e.y * wa.w + e.z * wb.y + e.w * wb.w;
    float nr = e.x * e.x + e.y * e.y + e.z * e.z + e.w * e.w;
    #pragma unroll
    for (int o = 8; o >= 1; o >>= 1) {
        l0 += __shfl_xor_sync(0xffffffffu, l0, o);
        l1 += __shfl_xor_sync(0xffffffffu, l1, o);
        nr += __shfl_xor_sync(0xffffffffu, nr, o);
    }
    if ((f & 15) == 0) {
        int v = x[pos];
        g_v[0][pos] = (unsigned char)v;
        l0 += llrb[0]; l1 += llrb[1];
        float m = fmaxf(l0, l1);
        float x0 = expf(l0 - m), x1 = expf(l1 - m);
        float inv = 1.f / (x0 + x1);
        float p0 = x0 * inv, p1 = x1 * inv;
        float pt = v ? p1 : p0;
        float loss = -logf(fminf(fmaxf(pt, 1e-7f), 1.f));
        int b = pos >> 10, p = pos & 1023;
        out[(size_t)b * (11 * N_) + p] = loss;
        float2* pr = (float2*)(out + PRED_OFF + (((size_t)(b * N_ + p)) * 11) * 2);
        *pr = make_float2(p0, p1);
        out[NORM_OFF + (size_t)b * (11 * N_) + p] = sqrtf(nr);
    }
}

// ---------------- main butterfly-stage kernel: 4 independent 4-warp pipelines ----------------
__global__ void __launch_bounds__(512, 1)
stage_kernel(int scope, int src, int s,
             const float* __restrict__ llrW, const float* __restrict__ llrb,
             float* __restrict__ out) {
    extern __shared__ char smp[];
    const u32 smb = smem_u32(smp);
    float* sT  = (float*)(smp + OT);
    float* sB1 = (float*)(smp + OB1);
    float* sB2 = (float*)(smp + OB2);
    float* sLW = (float*)(smp + OLW);
    __shared__ unsigned char sVx[4][32], sVe[4][32];

    const int tid = threadIdx.x;

    {   // stage weights: W1 hi/lo (272B rows) and W2 (144B rows) into smem
        #pragma unroll
        for (int it = 0; it < 4; it++) {
            int i = tid + it * 512;          // 2048 uint4 per buffer
            int j = i >> 4, c = i & 15;
            uint4 v1 = ((const uint4*)g_W1hi)[i];
            uint4 v2 = ((const uint4*)g_W1lo)[i];
            *(uint4*)(smp + OW1H + j * 272 + c * 16) = v1;
            *(uint4*)(smp + OW1L + j * 272 + c * 16) = v2;
            int mt = i >> 9, rem = i & 511;
            int j2 = rem >> 3, c2 = rem & 7;
            uint4 v3 = ((const uint4*)g_W2i)[mt * 512 + j2 * 8 + c2];
            *(uint4*)(smp + OW2 + mt * 9216 + j2 * 144 + c2 * 16) = v3;
        }
        if (tid < 128) { sT[tid] = g_T[tid]; sB1[tid] = g_B1[tid]; sB2[tid] = g_B2[tid]; sLW[tid] = llrW[tid]; }
    }
    __syncthreads();

    const int hsc = scope >> 1;              // half-scope
    const int dst = src ^ 1;
    const int pid = tid >> 7;                // pipeline 0..3
    const int lt  = tid & 127;               // thread within pipeline
    const int w = lt >> 5, l = lt & 31;      // local warp 0..3, lane
    const int hbar = 1 + pid;

    // GEMM1 grid (per pipeline): 1m x 4n, warp = 32 rows x 32 cols over [32 x 128]
    const int n0 = w * 32;
    const int side1 = w >> 1;
    // GEMM2 grid: 2m x 2side, warp = 16 rows x 64 cols
    const int wm2 = w & 1, side2 = w >> 1;
    const int r0b = wm2 * 16;
    const float lb0 = llrb[0], lb1 = llrb[1];

    const u32 xb  = smb + pid * XPIPE;       // X hi (32 x 272B)
    const u32 xbl = xb + 8704;               // X lo
    char* xbp  = smp + pid * XPIPE;
    char* xblp = xbp + 8704;

    // ldmatrix per-thread components (byte offsets)
    const int aoff  = (l & 15) * 272 + (l >> 4) * 16;
    const int boff1 = ((l & 7) + ((l >> 1) & 8) + n0) * 272 + (l & 8) * 2;
    const int aoff2 = (r0b + (l & 15)) * 272 + (side2 * 64 + ((l >> 4) << 3)) * 2;
    const int boff2 = ((l & 7) + ((l >> 1) & 8)) * 144 + (l & 8) * 2;
    const u32 w2hiB = smb + OW2 + side2 * 18432;

    // stmatrix per-thread address base (rows/cols within warp's 32x32 output)
    const int stile = l >> 3;
    const int soff = ((stile & 1) * 8 + (l & 7)) * 272 + (n0 + (stile >> 1) * 8) * 2;

    #define HBAR() asm volatile("bar.sync %0, 128;" :: "r"(hbar) : "memory")

    for (int tile = blockIdx.x * 4 + pid; tile < NT4; tile += 608) {
        int b  = tile >> 4;
        int j0 = (tile & 15) << 5;           // 32-pair tile base within batch
        const float* eb = g_e[src] + (size_t)b * (N_ * 64);
        const unsigned char* vb = g_v[src] + b * N_;

        // ---- bits ----
        if (lt < 32) {
            int j = j0 + lt;
            int so = ((j & ~(hsc - 1)) << 1) | (j & (hsc - 1));
            unsigned char vo = vb[so], ve = vb[so + hsc];
            sVx[pid][lt] = (unsigned char)((vo + ve) & 1);
            sVe[pid][lt] = ve;
        }
        // ---- gather X (32 pairs x 128 dims) as bf16 hi/lo ----
        #pragma unroll
        for (int it = 0; it < 4; it++) {
            int c  = lt + (it << 7);         // 0..511
            int r  = c >> 4;
            int f8 = c & 15;
            int hs = f8 >> 3;
            int j  = j0 + r;
            int so = ((j & ~(hsc - 1)) << 1) | (j & (hsc - 1));
            const float* p = eb + (size_t)(so + hs * hsc) * 64 + ((f8 & 7) << 3);
            float4 v0 = *(const float4*)p;
            float4 v1 = *(const float4*)(p + 4);
            uint4 H, L;
            H.x = pkhi(v0.x, v0.y, L.x); H.y = pkhi(v0.z, v0.w, L.y);
            H.z = pkhi(v1.x, v1.y, L.z); H.w = pkhi(v1.z, v1.w, L.w);
            int ad = r * 272 + f8 * 16;
            *(uint4*)(xbp + ad)  = H;
            *(uint4*)(xblp + ad) = L;
        }
        HBAR();

        // ---- GEMM1: C[32x128] = X @ W1T^T, 3-term bf16 split, warp 32x32 ----
        float acc[2][4][4];
        #pragma unroll
        for (int mt = 0; mt < 2; mt++)
            #pragma unroll
            for (int nt = 0; nt < 4; nt++)
                #pragma unroll
                for (int q = 0; q < 4; q++) acc[mt][nt][q] = 0.f;

        #pragma unroll
        for (int kc = 0; kc < 8; kc++) {
            int kb = kc * 32;
            u32 ah[2][4], al[2][4];
            #pragma unroll
            for (int mt = 0; mt < 2; mt++) {
                ldsm4(xb + aoff + mt * 16 * 272 + kb,  ah[mt][0], ah[mt][1], ah[mt][2], ah[mt][3]);
                ldsm4(xbl + aoff + mt * 16 * 272 + kb, al[mt][0], al[mt][1], al[mt][2], al[mt][3]);
            }
            #pragma unroll
            for (int np = 0; np < 2; np++) {
                u32 bh[4], bl[4];
                ldsm4(smb + OW1H + boff1 + np * 16 * 272 + kb, bh[0], bh[1], bh[2], bh[3]);
                ldsm4(smb + OW1L + boff1 + np * 16 * 272 + kb, bl[0], bl[1], bl[2], bl[3]);
                #pragma unroll
                for (int mt = 0; mt < 2; mt++) {
                    #pragma unroll
                    for (int hh = 0; hh < 2; hh++) {
                        float* c = acc[mt][np * 2 + hh];
                        mma16816(c, ah[mt], bh[2 * hh], bh[2 * hh + 1]);
                        mma16816(c, ah[mt], bl[2 * hh], bl[2 * hh + 1]);
                        mma16816(c, al[mt], bh[2 * hh], bh[2 * hh + 1]);
                    }
                }
            }
        }
        HBAR();   // all reads of X done before H overwrites it

        // ---- epilogue1: h = relu(C + b1 + T[vx]) -> H bf16 hi/lo via stmatrix ----
        #pragma unroll
        for (int mt = 0; mt < 2; mt++) {
            int rowa = mt * 16 + (l >> 2);
            int rowb = rowa + 8;
            int va = sVx[pid][rowa], vbt = sVx[pid][rowb];
            u32 HI01[4], HI23[4], LO01[4], LO23[4];
            #pragma unroll
            for (int nt = 0; nt < 4; nt++) {
                float* c = acc[mt][nt];
                int col = n0 + nt * 8 + (l & 3) * 2;
                float b0 = sB1[col], b1v = sB1[col + 1];
                float v00 = c[0] + b0, v01 = c[1] + b1v;
                float v10 = c[2] + b0, v11 = c[3] + b1v;
                if (side1) {
                    int tcol = col - 64;
                    v00 += sT[va * 64 + tcol];  v01 += sT[va * 64 + tcol + 1];
                    v10 += sT[vbt * 64 + tcol]; v11 += sT[vbt * 64 + tcol + 1];
                }
                v00 = fmaxf(v00, 0.f); v01 = fmaxf(v01, 0.f);
                v10 = fmaxf(v10, 0.f); v11 = fmaxf(v11, 0.f);
                HI01[nt] = pkhi(v00, v01, LO01[nt]);
                HI23[nt] = pkhi(v10, v11, LO23[nt]);
            }
            #pragma unroll
            for (int ntp = 0; ntp < 2; ntp++) {
                u32 sa = soff + mt * 16 * 272 + ntp * 32;
                stsm4(xb + sa,  HI01[2*ntp], HI23[2*ntp], HI01[2*ntp+1], HI23[2*ntp+1]);
                stsm4(xbl + sa, LO01[2*ntp], LO23[2*ntp], LO01[2*ntp+1], LO23[2*ntp+1]);
            }
        }
        HBAR();

        // ---- GEMM2: per side [32x64] = H_side @ W2_side; warp = 16 rows x 64 cols ----
        float acc2[8][4];
        #pragma unroll
        for (int nt = 0; nt < 8; nt++)
            #pragma unroll
            for (int q = 0; q < 4; q++) acc2[nt][q] = 0.f;

        #pragma unroll
        for (int kc = 0; kc < 4; kc++) {
            int kb = kc * 32;
            u32 ah[4], al[4];
            ldsm4(xb + aoff2 + kb,  ah[0], ah[1], ah[2], ah[3]);
            ldsm4(xbl + aoff2 + kb, al[0], al[1], al[2], al[3]);
            #pragma unroll
            for (int np = 0; np < 4; np++) {
                u32 bh[4], bl[4];
                ldsm4(w2hiB + boff2 + np * 16 * 144 + kb, bh[0], bh[1], bh[2], bh[3]);
                ldsm4(w2hiB + 9216 + boff2 + np * 16 * 144 + kb, bl[0], bl[1], bl[2], bl[3]);
                #pragma unroll
                for (int hh = 0; hh < 2; hh++) {
                    float* c = acc2[np * 2 + hh];
                    mma16816(c, ah, bh[2 * hh], bh[2 * hh + 1]);
                    mma16816(c, ah, bl[2 * hh], bl[2 * hh + 1]);
                    mma16816(c, al, bh[2 * hh], bh[2 * hh + 1]);
                }
            }
        }

        // ---- epilogue2: bias + e' store + fused head ----
        {
            float L0[2] = {0.f, 0.f}, L1[2] = {0.f, 0.f}, NR[2] = {0.f, 0.f};
            int rowa = r0b + (l >> 2);
            int pa = ((j0 + rowa) << 1) | side2;
            int pb = ((j0 + rowa + 8) << 1) | side2;
            float* ea  = g_e[dst] + ((size_t)b * N_ + pa) * 64;
            float* ebp = g_e[dst] + ((size_t)b * N_ + pb) * 64;
            #pragma unroll
            for (int nt = 0; nt < 8; nt++) {
                float* c = acc2[nt];
                int col = nt * 8 + (l & 3) * 2;
                float b0 = sB2[side2 * 64 + col], b1v = sB2[side2 * 64 + col + 1];
                float o00 = c[0] + b0, o01 = c[1] + b1v;
                float o10 = c[2] + b0, o11 = c[3] + b1v;
                *(float2*)(ea + col)  = make_float2(o00, o01);
                *(float2*)(ebp + col) = make_float2(o10, o11);
                float w0 = sLW[col * 2], w1 = sLW[col * 2 + 1];
                float w2 = sLW[col * 2 + 2], w3 = sLW[col * 2 + 3];
                L0[0] += o00 * w0 + o01 * w2;
                L1[0] += o00 * w1 + o01 * w3;
                NR[0] += o00 * o00 + o01 * o01;
                L0[1] += o10 * w0 + o11 * w2;
                L1[1] += o10 * w1 + o11 * w3;
                NR[1] += o10 * o10 + o11 * o11;
            }
            #pragma unroll
            for (int off = 2; off >= 1; off >>= 1) {
                #pragma unroll
                for (int hh = 0; hh < 2; hh++) {
                    L0[hh] += __shfl_xor_sync(0xffffffffu, L0[hh], off);
                    L1[hh] += __shfl_xor_sync(0xffffffffu, L1[hh], off);
                    NR[hh] += __shfl_xor_sync(0xffffffffu, NR[hh], off);
                }
            }
            if ((l & 3) == 0) {
                #pragma unroll
                for (int hh = 0; hh < 2; hh++) {
                    int r = r0b + (l >> 2) + hh * 8;
                    int p = ((j0 + r) << 1) | side2;
                    unsigned char vp = side2 ? sVe[pid][r] : sVx[pid][r];
                    g_v[dst][b * N_ + p] = vp;
                    float l0 = L0[hh] + lb0, l1 = L1[hh] + lb1;
                    float mm = fmaxf(l0, l1);
                    float x0 = expf(l0 - mm), x1 = expf(l1 - mm);
                    float inv = 1.f / (x0 + x1);
                    float p0 = x0 * inv, p1 = x1 * inv;
                    float pt = vp ? p1 : p0;
                    float loss = -logf(fminf(fmaxf(pt, 1e-7f), 1.f));
                    out[(size_t)b * (11 * N_) + (size_t)s * N_ + p] = loss;
                    float2* pr = (float2*)(out + PRED_OFF + (((size_t)(b * N_ + p)) * 11 + s) * 2);
                    *pr = make_float2(p0, p1);
                    out[NORM_OFF + (size_t)b * (11 * N_) + (size_t)s * N_ + p] = sqrtf(NR[hh]);
                }
            }
        }
        HBAR();   // protect X buffer + bits before next tile
    }
    #undef HBAR
}

// ---------------- launch ----------------
extern "C" void kernel_launch(void* const* d_in, const int* in_sizes, int n_in,
                              void* d_out, int out_size) {
    const int*   x    = (const int*)d_in[0];
    const float* y    = (const float*)d_in[1];
    const float* embW = (const float*)d_in[2];
    const float* embb = (const float*)d_in[3];
    const float* lab  = (const float*)d_in[4];
    const float* cnW1 = (const float*)d_in[5];
    const float* cnb1 = (const float*)d_in[6];
    const float* cnW2 = (const float*)d_in[7];
    const float* cnb2 = (const float*)d_in[8];
    const float* bnW1 = (const float*)d_in[9];
    const float* bnb1 = (const float*)d_in[10];
    const float* bnW2 = (const float*)d_in[11];
    const float* bnb2 = (const float*)d_in[12];
    const float* llrW = (const float*)d_in[13];
    const float* llrb = (const float*)d_in[14];
    float* out = (float*)d_out;

    cudaFuncSetAttribute(stage_kernel, cudaFuncAttributeMaxDynamicSharedMemorySize, DSMEM_BYTES);

    prep_kernel<<<1, 256>>>(cnW1, bnW1, cnW2, bnW2, cnb1, bnb1, cnb2, bnb2, lab);
    stage0_kernel<<<(B_ * N_ * 16) / 256, 256>>>(x, y, embW, embb, llrW, llrb, out);
    for (int s = 1; s <= 10; s++) {
        stage_kernel<<<152, 512, DSMEM_BYTES>>>(1 << s, (s - 1) & 1, s, llrW, llrb, out);
    }
}